// round 17
// baseline (speedup 1.0000x reference)
#include <cuda_runtime.h>
#include <cuda_fp16.h>
#include <math.h>

// Problem constants
#define BB     2
#define HEADS  8
#define LEVELS 3
#define POINTS 4
#define CC     256
#define HD     32          // CC / HEADS
#define NV     5376        // 64*64 + 32*32 + 16*16
#define NQ     5376
#define TP     96          // HEADS*LEVELS*POINTS
#define TP2    192
#define NBQH   (BB * NQ * HEADS)   // 86016

// Padded value-tensor geometry (1-cell zero ring per level).
#define PNV    5836
#define P0     0
#define P1     4356
#define P2     5512
#define VP_TOTAL  (BB * PNV * CC)      // 2,988,032 elements

// Scratch — g_vph is HEAD-MAJOR: ((b*HEADS+h)*PNV + pcell)*HD + hd
__device__ __half  g_vph[VP_TOTAL];
__device__ float   g_off[BB * NQ * TP2];
__device__ float   g_a[BB * NQ * TP];
__device__ float   g_tmp[BB * NQ * CC];    // sampled output (b, q, h, hd)
__device__ float4  g_w4[12 * NBQH];        // premult corner weights, [pp][bqh]
__device__ int     g_pidx[12 * NBQH];      // folded element-index of corner(0,0)

// ---------------------------------------------------------------------------
__global__ void __launch_bounds__(256) zero_vp_kernel()
{
    int i = blockIdx.x * blockDim.x + threadIdx.x;
    if (i < VP_TOTAL / 8)
        ((uint4*)g_vph)[i] = make_uint4(0u, 0u, 0u, 0u);
}

// ---------------------------------------------------------------------------
// Tensor-core GEMM (tf32 mma.sync), R9/R16 body.
// mode 0: C[m,n] fp32.   mode 1: fp16 head-major padded g_vph epilogue.
// mode 2: combined columns — n <  Nsplit -> W/bias/C   (stride Nsplit)
//                            n >= Nsplit -> W2/bias2/C2 (stride N-Nsplit)
// m_base: global row offset (for half-M launches).
// ---------------------------------------------------------------------------
#define GBm 128
#define GBn 64
#define GBk 32
#define SSTR 36

__device__ __forceinline__ unsigned f2tf32(float f) {
    unsigned u;
    asm("cvt.rna.tf32.f32 %0, %1;" : "=r"(u) : "f"(f));
    return u;
}

__device__ __forceinline__ int padded_cell(int n) {
    if (n < 4096)      { int y = n >> 6, x = n & 63;                   return P0 + (y + 1) * 66 + (x + 1); }
    else if (n < 5120) { int t = n - 4096; int y = t >> 5, x = t & 31; return P1 + (y + 1) * 34 + (x + 1); }
    else               { int t = n - 5120; int y = t >> 4, x = t & 15; return P2 + (y + 1) * 18 + (x + 1); }
}

__global__ void __launch_bounds__(256, 2) gemm_tf32_kernel(
    const float* __restrict__ A, const float* __restrict__ W,
    const float* __restrict__ bias, float* __restrict__ C,
    int M, int N, int K, int mode, int m_base,
    const float* __restrict__ W2, const float* __restrict__ bias2,
    float* __restrict__ C2, int Nsplit)
{
    __shared__ unsigned As[GBm][SSTR];
    __shared__ unsigned Ws[GBn][SSTR];

    const int tid  = threadIdx.x;
    const int lane = tid & 31;
    const int warp = tid >> 5;
    const int wm   = warp >> 1;
    const int wn   = warp & 1;
    const int m0   = blockIdx.y * GBm;
    const int n0   = blockIdx.x * GBn;

    const int grp = lane >> 2;
    const int tig = lane & 3;

    int ar[4], ac[4];
    size_t aoff[4];
#pragma unroll
    for (int j = 0; j < 4; j++) {
        int idx = tid + j * 256;
        ar[j] = idx >> 3;
        ac[j] = idx & 7;
        aoff[j] = (size_t)(m_base + m0 + ar[j]) * K + ac[j] * 4;
    }
    // W-tile per-thread row pointers (2 rows per thread)
    int wr[2], wc[2];
    bool wvalid[2];
    const float* wp[2];
#pragma unroll
    for (int j = 0; j < 2; j++) {
        int idx = tid + j * 256;
        wr[j] = idx >> 3;
        wc[j] = idx & 7;
        int r = n0 + wr[j];
        wvalid[j] = (r < N);
        int rc = wvalid[j] ? r : 0;
        if (mode == 2 && rc >= Nsplit)
            wp[j] = W2 + (size_t)(rc - Nsplit) * K + wc[j] * 4;
        else
            wp[j] = W + (size_t)rc * K + wc[j] * 4;
    }

    float c[2][4][4];
#pragma unroll
    for (int mt = 0; mt < 2; mt++)
#pragma unroll
        for (int nt = 0; nt < 4; nt++)
#pragma unroll
            for (int i = 0; i < 4; i++) c[mt][nt][i] = 0.f;

    float4 pa[4], pw[2];
#pragma unroll
    for (int j = 0; j < 4; j++) pa[j] = *(const float4*)&A[aoff[j]];
#pragma unroll
    for (int j = 0; j < 2; j++)
        pw[j] = wvalid[j] ? *(const float4*)(wp[j]) : make_float4(0.f, 0.f, 0.f, 0.f);

    for (int k0 = 0; k0 < K; k0 += GBk) {
#pragma unroll
        for (int j = 0; j < 4; j++) {
            uint4 u;
            u.x = f2tf32(pa[j].x); u.y = f2tf32(pa[j].y);
            u.z = f2tf32(pa[j].z); u.w = f2tf32(pa[j].w);
            *(uint4*)&As[ar[j]][ac[j] * 4] = u;
        }
#pragma unroll
        for (int j = 0; j < 2; j++) {
            uint4 u;
            u.x = f2tf32(pw[j].x); u.y = f2tf32(pw[j].y);
            u.z = f2tf32(pw[j].z); u.w = f2tf32(pw[j].w);
            *(uint4*)&Ws[wr[j]][wc[j] * 4] = u;
        }
        __syncthreads();

        const int kn = k0 + GBk;
        if (kn < K) {
#pragma unroll
            for (int j = 0; j < 4; j++) pa[j] = *(const float4*)&A[aoff[j] + kn];
#pragma unroll
            for (int j = 0; j < 2; j++)
                pw[j] = wvalid[j] ? *(const float4*)(wp[j] + kn)
                                  : make_float4(0.f, 0.f, 0.f, 0.f);
        }

#pragma unroll
        for (int kk = 0; kk < GBk; kk += 8) {
            unsigned a[2][4];
#pragma unroll
            for (int mt = 0; mt < 2; mt++) {
                int rb = wm * 32 + mt * 16;
                a[mt][0] = As[rb + grp][kk + tig];
                a[mt][1] = As[rb + grp + 8][kk + tig];
                a[mt][2] = As[rb + grp][kk + tig + 4];
                a[mt][3] = As[rb + grp + 8][kk + tig + 4];
            }
            unsigned b[4][2];
#pragma unroll
            for (int nt = 0; nt < 4; nt++) {
                int cb = wn * 32 + nt * 8;
                b[nt][0] = Ws[cb + grp][kk + tig];
                b[nt][1] = Ws[cb + grp][kk + tig + 4];
            }
#pragma unroll
            for (int mt = 0; mt < 2; mt++)
#pragma unroll
                for (int nt = 0; nt < 4; nt++) {
                    asm volatile(
                        "mma.sync.aligned.m16n8k8.row.col.f32.tf32.tf32.f32 "
                        "{%0,%1,%2,%3}, {%4,%5,%6,%7}, {%8,%9}, {%0,%1,%2,%3};"
                        : "+f"(c[mt][nt][0]), "+f"(c[mt][nt][1]),
                          "+f"(c[mt][nt][2]), "+f"(c[mt][nt][3])
                        : "r"(a[mt][0]), "r"(a[mt][1]), "r"(a[mt][2]), "r"(a[mt][3]),
                          "r"(b[nt][0]), "r"(b[nt][1]));
                }
        }
        __syncthreads();
    }

    // ---- epilogue ----
    int pb[2], pc0[2], pc1[2];
#pragma unroll
    for (int mt = 0; mt < 2; mt++) {
        int gm = m_base + m0 + wm * 32 + mt * 16 + grp;
        if (mode == 1) {
            int b = gm / NV;
            pb[mt]  = b;
            pc0[mt] = padded_cell(gm - b * NV);
            pc1[mt] = padded_cell(gm + 8 - b * NV);
        } else {
            pb[mt] = 0; pc0[mt] = gm; pc1[mt] = gm + 8;
        }
    }
#pragma unroll
    for (int nt = 0; nt < 4; nt++) {
        int gn = n0 + wn * 32 + nt * 8 + tig * 2;
        if (gn >= N) continue;
        float b0, b1;
        float* dst;
        int stride, col;
        if (mode == 2 && gn >= Nsplit) {
            col = gn - Nsplit; dst = C2; stride = N - Nsplit;
            b0 = bias2[col]; b1 = bias2[col + 1];
        } else {
            col = gn; dst = C; stride = (mode == 2) ? Nsplit : N;
            b0 = bias[gn]; b1 = bias[gn + 1];
        }
#pragma unroll
        for (int mt = 0; mt < 2; mt++) {
            float2 o0 = make_float2(c[mt][nt][0] + b0, c[mt][nt][1] + b1);
            float2 o1 = make_float2(c[mt][nt][2] + b0, c[mt][nt][3] + b1);
            if (mode == 1) {
                const int h  = gn >> 5;
                const int hd = gn & 31;
                const size_t i0 = ((size_t)(pb[mt] * HEADS + h) * PNV + pc0[mt]) * HD + hd;
                const size_t i1 = ((size_t)(pb[mt] * HEADS + h) * PNV + pc1[mt]) * HD + hd;
                *(__half2*)&g_vph[i0] = __floats2half2_rn(o0.x, o0.y);
                *(__half2*)&g_vph[i1] = __floats2half2_rn(o1.x, o1.y);
            } else {
                *(float2*)&dst[(size_t)pc0[mt] * stride + col] = o0;
                *(float2*)&dst[(size_t)pc1[mt] * stride + col] = o1;
            }
        }
    }
}

// ---------------------------------------------------------------------------
// Precompute: softmax + sampling coordinates/weights, once per (b,q,h).
// idx00 head-major: ((b*HEADS + h)*PNV + cell00) * HD     (unchanged from R16)
// ---------------------------------------------------------------------------
__global__ void __launch_bounds__(256) precompute_kernel(
    const float* __restrict__ refpts)
{
    const int t = blockIdx.x * blockDim.x + threadIdx.x;
    if (t >= NBQH) return;
    const int h  = t % HEADS;
    const int bq = t / HEADS;
    const int b  = bq / NQ;

    const float rx = refpts[bq * 2 + 0];
    const float ry = refpts[bq * 2 + 1];

    const float* __restrict__ off   = g_off + bq * TP2 + h * (LEVELS * POINTS * 2);
    const float* __restrict__ logit = g_a   + bq * TP  + h * (LEVELS * POINTS);

    float e[12];
    float mx = -INFINITY;
#pragma unroll
    for (int i = 0; i < 12; i++) { e[i] = logit[i]; mx = fmaxf(mx, e[i]); }
    float s = 0.f;
#pragma unroll
    for (int i = 0; i < 12; i++) { e[i] = __expf(e[i] - mx); s += e[i]; }
    const float inv = 1.f / s;

    const int plvl_start[LEVELS] = {P0, P1, P2};
    const int lvl_dim[LEVELS]    = {64, 32, 16};

    const int hbase = (b * HEADS + h) * PNV;

#pragma unroll
    for (int lvl = 0; lvl < LEVELS; lvl++) {
        const int Wd = lvl_dim[lvl];
        const int Pw = Wd + 2;
        const float fW = (float)Wd;
#pragma unroll
        for (int p = 0; p < POINTS; p++) {
            const int pp = lvl * POINTS + p;
            float lx = rx + off[pp * 2 + 0];
            float ly = ry + off[pp * 2 + 1];
            lx = fminf(fmaxf(lx, 0.f), 1.f);
            ly = fminf(fmaxf(ly, 0.f), 1.f);
            const float aw = e[pp] * inv;

            const float x = lx * fW - 0.5f;
            const float y = ly * fW - 0.5f;
            const float x0f = floorf(x);
            const float y0f = floorf(y);
            const int x0 = (int)x0f;
            const int y0 = (int)y0f;
            const float wx1 = x - x0f;
            const float wy1 = y - y0f;
            const float wx0 = 1.f - wx1;
            const float wy0 = 1.f - wy1;

            float4 w4;
            w4.x = aw * wx0 * wy0;
            w4.y = aw * wx1 * wy0;
            w4.z = aw * wx0 * wy1;
            w4.w = aw * wx1 * wy1;

            const int cell00 = plvl_start[lvl] + (y0 + 1) * Pw + (x0 + 1);
            const int idx00  = (hbase + cell00) * HD;

            g_w4 [pp * NBQH + t] = w4;
            g_pidx[pp * NBQH + t] = idx00;
        }
    }
}

// ---------------------------------------------------------------------------
// Bilinear sampling over head-major fp16 v (R16 body) + warp_base for halves.
// ---------------------------------------------------------------------------
__global__ void __launch_bounds__(256) sample_kernel(int warp_base)
{
    const int warp = warp_base + ((blockIdx.x * blockDim.x + threadIdx.x) >> 5);
    const int lane = threadIdx.x & 31;
    if (warp >= NBQH) return;

    const int pt = (lane >> 4) & 1;
    const int cg = (lane >> 2) & 3;
    const int q  = lane & 3;
    const int dx = cg & 1;
    const int dy = cg >> 1;

    const int coff0 = (dy * 66 + dx) * HD + q * 8;
    const int coff1 = (dy * 34 + dx) * HD + q * 8;
    const int coff2 = (dy * 18 + dx) * HD + q * 8;

    float acc[8];
#pragma unroll
    for (int j = 0; j < 8; j++) acc[j] = 0.f;

#pragma unroll
    for (int i = 0; i < 6; i++) {
        const int pp = 2 * i + pt;
        const float4 w4  = g_w4 [pp * NBQH + warp];
        const int  idx00 = g_pidx[pp * NBQH + warp];

        const float w = (cg == 0) ? w4.x : (cg == 1) ? w4.y
                      : (cg == 2) ? w4.z : w4.w;

        const int coff = (i < 2) ? coff0 : (i < 4) ? coff1 : coff2;
        const uint4 raw = *(const uint4*)&g_vph[idx00 + coff];

        const __half2* h2 = (const __half2*)&raw;
#pragma unroll
        for (int j = 0; j < 4; j++) {
            const float2 f = __half22float2(h2[j]);
            acc[2 * j + 0] = fmaf(w, f.x, acc[2 * j + 0]);
            acc[2 * j + 1] = fmaf(w, f.y, acc[2 * j + 1]);
        }
    }

#pragma unroll
    for (int ofs = 4; ofs <= 16; ofs <<= 1) {
#pragma unroll
        for (int j = 0; j < 8; j++)
            acc[j] += __shfl_xor_sync(0xffffffffu, acc[j], ofs);
    }

    if (lane < 4) {
        float* dst = &g_tmp[warp * HD + q * 8];
        *(float4*)&dst[0] = make_float4(acc[0], acc[1], acc[2], acc[3]);
        *(float4*)&dst[4] = make_float4(acc[4], acc[5], acc[6], acc[7]);
    }
}

// ---------------------------------------------------------------------------
extern "C" void kernel_launch(void* const* d_in, const int* in_sizes, int n_in,
                              void* d_out, int out_size)
{
    const float* query  = (const float*)d_in[0];
    const float* refpts = (const float*)d_in[1];
    const float* value  = (const float*)d_in[2];
    const float* Wv     = (const float*)d_in[3];
    const float* bv     = (const float*)d_in[4];
    const float* Woff   = (const float*)d_in[5];
    const float* boff   = (const float*)d_in[6];
    const float* Wa     = (const float*)d_in[7];
    const float* ba     = (const float*)d_in[8];
    const float* Wo     = (const float*)d_in[9];
    const float* bo     = (const float*)d_in[10];
    float* out = (float*)d_out;

    float *p_off, *p_a, *p_tmp;
    cudaGetSymbolAddress((void**)&p_off, g_off);
    cudaGetSymbolAddress((void**)&p_a,   g_a);
    cudaGetSymbolAddress((void**)&p_tmp, g_tmp);

    static cudaStream_t s1 = nullptr, s2 = nullptr;
    static cudaEvent_t ev_root = nullptr, ev_pre = nullptr, ev_sh1 = nullptr, ev_o1 = nullptr;
    if (!s1) {
        cudaStreamCreateWithFlags(&s1, cudaStreamNonBlocking);
        cudaStreamCreateWithFlags(&s2, cudaStreamNonBlocking);
        cudaEventCreateWithFlags(&ev_root, cudaEventDisableTiming);
        cudaEventCreateWithFlags(&ev_pre,  cudaEventDisableTiming);
        cudaEventCreateWithFlags(&ev_sh1,  cudaEventDisableTiming);
        cudaEventCreateWithFlags(&ev_o1,   cudaEventDisableTiming);
    }

    const int M  = BB * NQ;             // 10752 = 84 * 128
    const int gy = M / GBm;             // 84
    const int Mh = M / 2;               // 5376
    const int gyh = gy / 2;             // 42

    // Fork
    cudaEventRecord(ev_root, 0);
    cudaStreamWaitEvent(s1, ev_root, 0);

    // Main stream: zero padded v buffer, then v-GEMM (fp16 head-major epilogue).
    zero_vp_kernel<<<(VP_TOTAL / 8 + 255) / 256, 256>>>();
    gemm_tf32_kernel<<<dim3(CC / GBn, gy), 256>>>(
        value, Wv, bv, nullptr, M, CC, CC, 1, 0, nullptr, nullptr, nullptr, 0);

    // Side stream 1: combined off+a GEMM (N=288 split at 192), then precompute.
    gemm_tf32_kernel<<<dim3((TP2 + TP + GBn - 1) / GBn, gy), 256, 0, s1>>>(
        query, Woff, boff, p_off, M, TP2 + TP, CC, 2, 0, Wa, ba, p_a, TP2);
    precompute_kernel<<<(NBQH + 255) / 256, 256, 0, s1>>>(refpts);
    cudaEventRecord(ev_pre, s1);

    // Join for sampling: needs v (main, program order) + weights/indices (s1).
    cudaStreamWaitEvent(0, ev_pre, 0);

    // Pipelined sampling / out-GEMM:
    //   main: sample(half1) -> ev_sh1 -> sample(half2) -> out-GEMM(half2)
    //   s2:   wait ev_sh1   -> out-GEMM(half1)          -> ev_o1
    sample_kernel<<<(NBQH / 2) / 8, 256>>>(0);
    cudaEventRecord(ev_sh1, 0);
    sample_kernel<<<(NBQH / 2) / 8, 256>>>(NBQH / 2);

    cudaStreamWaitEvent(s2, ev_sh1, 0);
    gemm_tf32_kernel<<<dim3(CC / GBn, gyh), 256, 0, s2>>>(
        p_tmp, Wo, bo, out, M, CC, CC, 0, 0, nullptr, nullptr, nullptr, 0);
    cudaEventRecord(ev_o1, s2);

    gemm_tf32_kernel<<<dim3(CC / GBn, gyh), 256>>>(
        p_tmp, Wo, bo, out, M, CC, CC, 0, Mh, nullptr, nullptr, nullptr, 0);

    // Join the side branch back into the capture stream.
    cudaStreamWaitEvent(0, ev_o1, 0);
}